// round 2
// baseline (speedup 1.0000x reference)
#include <cuda_runtime.h>

// CumulantSOAP_CV: per-column mean & variance over X (200000 x 576 fp32),
// then project (cum - mu) @ W  -> (1 x 4).  HBM-bound streaming reduction.

#define N_ROWS   200000
#define P        576
#define NBLK     444                            // 3 CTAs/SM * 148 SMs
#define RPB      ((N_ROWS + NBLK - 1) / NBLK)   // 451 rows per block
#define NPART    (NBLK * 4)                     // 1776 partials per column

// Scratch (allocation-free). Transposed layout: partials contiguous per column.
__device__ float g_ps[P][NPART];   // partial sums       (4.1 MB)
__device__ float g_pq[P][NPART];   // partial sum-sqs    (4.1 MB)
__device__ float g_colsum[P];
__device__ float g_colsq[P];

// ---------------------------------------------------------------------------
// Pass 1: streaming reduction over X. blockDim = 576, grid = 444.
//   thread t -> column group c4 = t % 144 (4 columns via float4),
//               row phase   rs = t / 144 (0..3)
// Coalesced float4 streaming loads (__ldcs: read-once, evict-first).
// ---------------------------------------------------------------------------
__global__ __launch_bounds__(576) void pass1_kernel(const float* __restrict__ X) {
    const int b  = blockIdx.x;
    const int t  = threadIdx.x;
    const int c4 = t % 144;      // float4 column index (0..143)
    const int rs = t / 144;      // 0..3

    const int r0 = b * RPB;
    int r1 = r0 + RPB;
    if (r1 > N_ROWS) r1 = N_ROWS;

    const float4* __restrict__ Xv = reinterpret_cast<const float4*>(X);

    float4 s = make_float4(0.f, 0.f, 0.f, 0.f);
    float4 q = make_float4(0.f, 0.f, 0.f, 0.f);

    #pragma unroll 4
    for (int r = r0 + rs; r < r1; r += 4) {
        float4 x = __ldcs(&Xv[(size_t)r * 144 + c4]);
        s.x += x.x; s.y += x.y; s.z += x.z; s.w += x.w;
        q.x += x.x * x.x; q.y += x.y * x.y; q.z += x.z * x.z; q.w += x.w * x.w;
    }

    // Transposed scatter: column-major partial arrays (coalesced in pass2).
    const int p = b * 4 + rs;
    const int c0 = c4 * 4;
    g_ps[c0 + 0][p] = s.x;  g_ps[c0 + 1][p] = s.y;
    g_ps[c0 + 2][p] = s.z;  g_ps[c0 + 3][p] = s.w;
    g_pq[c0 + 0][p] = q.x;  g_pq[c0 + 1][p] = q.y;
    g_pq[c0 + 2][p] = q.z;  g_pq[c0 + 3][p] = q.w;
}

// ---------------------------------------------------------------------------
// Pass 2: one warp per column; contiguous float4 loads over the 1776 partials,
// deterministic shuffle tree. grid = 72 blocks x 256 threads (8 warps).
// ---------------------------------------------------------------------------
__global__ __launch_bounds__(256) void pass2_kernel() {
    const int w    = threadIdx.x >> 5;
    const int lane = threadIdx.x & 31;
    const int c    = blockIdx.x * 8 + w;     // column 0..575

    const float4* __restrict__ ps = reinterpret_cast<const float4*>(&g_ps[c][0]);
    const float4* __restrict__ pq = reinterpret_cast<const float4*>(&g_pq[c][0]);

    float4 s = make_float4(0.f, 0.f, 0.f, 0.f);
    float4 q = make_float4(0.f, 0.f, 0.f, 0.f);
    for (int i = lane; i < NPART / 4; i += 32) {
        float4 a = ps[i];
        s.x += a.x; s.y += a.y; s.z += a.z; s.w += a.w;
        float4 b = pq[i];
        q.x += b.x; q.y += b.y; q.z += b.z; q.w += b.w;
    }
    float ss = (s.x + s.y) + (s.z + s.w);
    float qq = (q.x + q.y) + (q.z + q.w);

    #pragma unroll
    for (int off = 16; off > 0; off >>= 1) {
        ss += __shfl_down_sync(0xffffffffu, ss, off);
        qq += __shfl_down_sync(0xffffffffu, qq, off);
    }
    if (lane == 0) { g_colsum[c] = ss; g_colsq[c] = qq; }
}

// ---------------------------------------------------------------------------
// Pass 3: cumulants, subtract mu, project by W (1728 x 4), reduce to out[4].
// One block, 576 threads. mom1 == 0 analytically (fp32 residual ~1e-7 is
// negligible at the 1e-3 output tolerance).
// ---------------------------------------------------------------------------
__global__ __launch_bounds__(576) void pass3_kernel(const float* __restrict__ mu,
                                                    const float* __restrict__ W,
                                                    float* __restrict__ out) {
    const int c = threadIdx.x;   // 0..575
    const float invN = 1.0f / (float)N_ROWS;

    const float m    = g_colsum[c] * invN;
    const float mom2 = g_colsq[c] * invN - m * m;

    const int j0 = 3 * c;
    const float d0 = m    - mu[j0 + 0];
    const float d1 = 0.f  - mu[j0 + 1];
    const float d2 = mom2 - mu[j0 + 2];

    float4 acc;
    acc.x = d0 * W[(j0 + 0) * 4 + 0] + d1 * W[(j0 + 1) * 4 + 0] + d2 * W[(j0 + 2) * 4 + 0];
    acc.y = d0 * W[(j0 + 0) * 4 + 1] + d1 * W[(j0 + 1) * 4 + 1] + d2 * W[(j0 + 2) * 4 + 1];
    acc.z = d0 * W[(j0 + 0) * 4 + 2] + d1 * W[(j0 + 1) * 4 + 2] + d2 * W[(j0 + 2) * 4 + 2];
    acc.w = d0 * W[(j0 + 0) * 4 + 3] + d1 * W[(j0 + 1) * 4 + 3] + d2 * W[(j0 + 2) * 4 + 3];

    __shared__ float4 sh[576];
    sh[c] = acc;
    __syncthreads();

    if (c < 64) {
        float4 a = sh[c];
        for (int i = c + 64; i < 576; i += 64) {
            float4 b = sh[i];
            a.x += b.x; a.y += b.y; a.z += b.z; a.w += b.w;
        }
        sh[c] = a;
    }
    __syncthreads();
    #pragma unroll
    for (int w = 32; w > 0; w >>= 1) {
        if (c < w) {
            float4 a = sh[c], b = sh[c + w];
            a.x += b.x; a.y += b.y; a.z += b.z; a.w += b.w;
            sh[c] = a;
        }
        __syncthreads();
    }

    if (c == 0) {
        out[0] = sh[0].x;
        out[1] = sh[0].y;
        out[2] = sh[0].z;
        out[3] = sh[0].w;
    }
}

extern "C" void kernel_launch(void* const* d_in, const int* in_sizes, int n_in,
                              void* d_out, int out_size) {
    (void)in_sizes; (void)n_in; (void)out_size;
    const float* X  = (const float*)d_in[0];   // (200000, 576)
    const float* mu = (const float*)d_in[1];   // (1728,)
    const float* W  = (const float*)d_in[2];   // (1728, 4)
    float* out = (float*)d_out;                // (1, 4)

    pass1_kernel<<<NBLK, 576>>>(X);
    pass2_kernel<<<72, 256>>>();
    pass3_kernel<<<1, 576>>>(mu, W, out);
}

// round 4
// speedup vs baseline: 1.0515x; 1.0515x over previous
#include <cuda_runtime.h>

// CumulantSOAP_CV: per-column mean & variance over X (200000 x 576 fp32),
// then project (cum - mu) @ W  -> (1 x 4).  HBM-bound streaming reduction.

#define N_ROWS   200000
#define P        576
#define NBLK     296
#define RPB      ((N_ROWS + NBLK - 1) / NBLK)   // 676 rows per block
#define NBLK2    16                              // pass2 grid

// Scratch (allocation-free). Row-major: row index = partial, col = feature.
__device__ float g_ps[NBLK][P];    // per-block partial sums      (0.68 MB)
__device__ float g_pq[NBLK][P];    // per-block partial sum-sqs   (0.68 MB)
__device__ float g_ps2[NBLK2][P];
__device__ float g_pq2[NBLK2][P];

// ---------------------------------------------------------------------------
// Pass 1: streaming reduction over X. blockDim = 576, grid = 296 (2 CTA/SM).
//   thread t -> column group c4 = t % 144 (4 columns via float4),
//               row phase   rs = t / 144 (0..3)
// Main loop identical to the 68us/86%-DRAM R1 version. Epilogue reduces the
// 4 row-phases through smem, then 144 coalesced float4 stores per block
// (row-major partials -> pass2 reads are coalesced too).
// ---------------------------------------------------------------------------
__global__ __launch_bounds__(576) void pass1_kernel(const float* __restrict__ X) {
    const int b  = blockIdx.x;
    const int t  = threadIdx.x;
    const int c4 = t % 144;      // float4 column index (0..143)
    const int rs = t / 144;      // 0..3

    const int r0 = b * RPB;
    int r1 = r0 + RPB;
    if (r1 > N_ROWS) r1 = N_ROWS;

    const float4* __restrict__ Xv = reinterpret_cast<const float4*>(X);

    float4 s = make_float4(0.f, 0.f, 0.f, 0.f);
    float4 q = make_float4(0.f, 0.f, 0.f, 0.f);

    #pragma unroll 4
    for (int r = r0 + rs; r < r1; r += 4) {
        float4 x = Xv[(size_t)r * 144 + c4];
        s.x += x.x; s.y += x.y; s.z += x.z; s.w += x.w;
        q.x += x.x * x.x; q.y += x.y * x.y; q.z += x.z * x.z; q.w += x.w * x.w;
    }

    // Reduce the 4 row-phases in shared memory (phases 1..3 park, phase 0 sums).
    __shared__ float4 sh_s[3][144];
    __shared__ float4 sh_q[3][144];
    if (rs > 0) { sh_s[rs - 1][c4] = s; sh_q[rs - 1][c4] = q; }
    __syncthreads();
    if (rs == 0) {
        #pragma unroll
        for (int ph = 0; ph < 3; ph++) {
            float4 a = sh_s[ph][c4];
            s.x += a.x; s.y += a.y; s.z += a.z; s.w += a.w;
            float4 bq = sh_q[ph][c4];
            q.x += bq.x; q.y += bq.y; q.z += bq.z; q.w += bq.w;
        }
        reinterpret_cast<float4*>(&g_ps[b][0])[c4] = s;
        reinterpret_cast<float4*>(&g_pq[b][0])[c4] = q;
    }
}

// ---------------------------------------------------------------------------
// Pass 2: fold 296 partial rows -> 16. grid = 16 blocks x 576 threads.
// Thread c owns column c; row reads are fully coalesced across the block.
// ---------------------------------------------------------------------------
__global__ __launch_bounds__(576) void pass2_kernel() {
    const int c = threadIdx.x;     // 0..575
    const int b = blockIdx.x;      // 0..15

    float s = 0.f, q = 0.f;
    for (int i = b; i < NBLK; i += NBLK2) {
        s += g_ps[i][c];
        q += g_pq[i][c];
    }
    g_ps2[b][c] = s;
    g_pq2[b][c] = q;
}

// ---------------------------------------------------------------------------
// Pass 3: fold last 16 rows, cumulants, subtract mu, project by W (1728 x 4),
// tree-reduce to out[4]. One block, 576 threads. mom1 == 0 analytically
// (reference's fp32 residual ~1e-7 is negligible at the 1e-3 tolerance).
// ---------------------------------------------------------------------------
__global__ __launch_bounds__(576) void pass3_kernel(const float* __restrict__ mu,
                                                    const float* __restrict__ W,
                                                    float* __restrict__ out) {
    const int c = threadIdx.x;   // 0..575
    const float invN = 1.0f / (float)N_ROWS;

    float s = 0.f, q = 0.f;
    #pragma unroll
    for (int i = 0; i < NBLK2; i++) {
        s += g_ps2[i][c];
        q += g_pq2[i][c];
    }

    const float m    = s * invN;
    const float mom2 = q * invN - m * m;

    const int j0 = 3 * c;
    const float d0 = m    - mu[j0 + 0];
    const float d1 = 0.f  - mu[j0 + 1];
    const float d2 = mom2 - mu[j0 + 2];

    float4 acc;
    acc.x = d0 * W[(j0 + 0) * 4 + 0] + d1 * W[(j0 + 1) * 4 + 0] + d2 * W[(j0 + 2) * 4 + 0];
    acc.y = d0 * W[(j0 + 0) * 4 + 1] + d1 * W[(j0 + 1) * 4 + 1] + d2 * W[(j0 + 2) * 4 + 1];
    acc.z = d0 * W[(j0 + 0) * 4 + 2] + d1 * W[(j0 + 1) * 4 + 2] + d2 * W[(j0 + 2) * 4 + 2];
    acc.w = d0 * W[(j0 + 0) * 4 + 3] + d1 * W[(j0 + 1) * 4 + 3] + d2 * W[(j0 + 2) * 4 + 3];

    __shared__ float4 sh[576];
    sh[c] = acc;
    __syncthreads();

    if (c < 64) {
        float4 a = sh[c];
        for (int i = c + 64; i < 576; i += 64) {
            float4 b = sh[i];
            a.x += b.x; a.y += b.y; a.z += b.z; a.w += b.w;
        }
        sh[c] = a;
    }
    __syncthreads();
    #pragma unroll
    for (int w = 32; w > 0; w >>= 1) {
        if (c < w) {
            float4 a = sh[c], b = sh[c + w];
            a.x += b.x; a.y += b.y; a.z += b.z; a.w += b.w;
            sh[c] = a;
        }
        __syncthreads();
    }

    if (c == 0) {
        out[0] = sh[0].x;
        out[1] = sh[0].y;
        out[2] = sh[0].z;
        out[3] = sh[0].w;
    }
}

extern "C" void kernel_launch(void* const* d_in, const int* in_sizes, int n_in,
                              void* d_out, int out_size) {
    (void)in_sizes; (void)n_in; (void)out_size;
    const float* X  = (const float*)d_in[0];   // (200000, 576)
    const float* mu = (const float*)d_in[1];   // (1728,)
    const float* W  = (const float*)d_in[2];   // (1728, 4)
    float* out = (float*)d_out;                // (1, 4)

    pass1_kernel<<<NBLK, 576>>>(X);
    pass2_kernel<<<NBLK2, 576>>>();
    pass3_kernel<<<1, 576>>>(mu, W, out);
}

// round 5
// speedup vs baseline: 1.0756x; 1.0229x over previous
#include <cuda_runtime.h>

// CumulantSOAP_CV: per-column mean & variance over X (200000 x 576 fp32),
// then project (cum - mu) @ W -> (1 x 4).  HBM-bound streaming reduction,
// fully fused into ONE kernel using a software grid barrier (grid = exactly
// one resident wave: 296 blocks = 148 SMs x 2 CTAs, guaranteed by
// __launch_bounds__(576, 2)).

#define N_ROWS   200000
#define P        576
#define NBLK     296
#define RPB      ((N_ROWS + NBLK - 1) / NBLK)   // 676 rows per block
#define NPART    (NBLK * 4)                     // 1184 partial rows
#define NRED     288                            // reducer blocks (2 cols each)

// Scratch (allocation-free __device__ globals).
__device__ float g_ps[NPART][P];   // partial sums      (2.7 MB, L2-resident)
__device__ float g_pq[NPART][P];   // partial sum-sqs   (2.7 MB)
__device__ float g_colsum[P];
__device__ float g_colsq[P];
__device__ int   g_cnt1;           // zero-init; reset by block 0 at kernel end
__device__ int   g_cnt2;

__global__ __launch_bounds__(576, 2)
void fused_kernel(const float* __restrict__ X,
                  const float* __restrict__ mu,
                  const float* __restrict__ W,
                  float* __restrict__ out) {
    const int b  = blockIdx.x;
    const int t  = threadIdx.x;
    const int c4 = t % 144;      // float4 column index (0..143)
    const int rs = t / 144;      // row phase (0..3)

    // ---------------- Phase 1: streaming reduction (identical to R1) -------
    const int r0 = b * RPB;
    int r1 = r0 + RPB;
    if (r1 > N_ROWS) r1 = N_ROWS;

    const float4* __restrict__ Xv = reinterpret_cast<const float4*>(X);

    float4 s = make_float4(0.f, 0.f, 0.f, 0.f);
    float4 q = make_float4(0.f, 0.f, 0.f, 0.f);

    #pragma unroll 4
    for (int r = r0 + rs; r < r1; r += 4) {
        float4 x = Xv[(size_t)r * 144 + c4];
        s.x += x.x; s.y += x.y; s.z += x.z; s.w += x.w;
        q.x += x.x * x.x; q.y += x.y * x.y; q.z += x.z * x.z; q.w += x.w * x.w;
    }

    const int p = b * 4 + rs;
    reinterpret_cast<float4*>(&g_ps[p][0])[c4] = s;
    reinterpret_cast<float4*>(&g_pq[p][0])[c4] = q;

    // ---------------- Grid barrier #1 --------------------------------------
    __threadfence();
    __syncthreads();
    if (t == 0) atomicAdd(&g_cnt1, 1);

    if (b >= NRED) return;            // 8 blocks arrive and exit

    if (t == 0) {
        while (*(volatile int*)&g_cnt1 < NBLK) __nanosleep(64);
        __threadfence();              // acquire: partials now visible
    }
    __syncthreads();

    // ---------------- Phase 2: fold 1184 partial rows per column ----------
    // Block b owns columns 2b and 2b+1; 256 threads per column.
    __shared__ float sh_s[2][256];
    __shared__ float sh_q[2][256];
    const int g = t >> 8;             // 0 or 1 (t<512), 2 for t>=512 (idle)
    const int l = t & 255;
    if (t < 512) {
        const int c = 2 * b + g;
        float ss = 0.f, qq = 0.f;
        for (int i = l; i < NPART; i += 256) {
            ss += g_ps[i][c];
            qq += g_pq[i][c];
        }
        sh_s[g][l] = ss; sh_q[g][l] = qq;
    }
    __syncthreads();
    #pragma unroll
    for (int w = 128; w > 0; w >>= 1) {
        if (t < 512 && l < w) {
            sh_s[g][l] += sh_s[g][l + w];
            sh_q[g][l] += sh_q[g][l + w];
        }
        __syncthreads();
    }
    if (t < 512 && l == 0) {
        const int c = 2 * b + g;
        g_colsum[c] = sh_s[g][0];
        g_colsq[c]  = sh_q[g][0];
    }

    // ---------------- Grid barrier #2 --------------------------------------
    __threadfence();
    __syncthreads();
    if (t == 0) atomicAdd(&g_cnt2, 1);

    if (b != 0) return;

    if (t == 0) {
        while (*(volatile int*)&g_cnt2 < NRED) __nanosleep(64);
        __threadfence();
    }
    __syncthreads();

    // ---------------- Phase 3: cumulants + projection (block 0) -----------
    // mom1 == 0 analytically (reference's fp32 residual ~1e-7 is negligible
    // at the 1e-3 output tolerance).
    const int c = t;                  // 0..575
    const float invN = 1.0f / (float)N_ROWS;

    const float m    = g_colsum[c] * invN;
    const float mom2 = g_colsq[c] * invN - m * m;

    const int j0 = 3 * c;
    const float d0 = m    - mu[j0 + 0];
    const float d1 = 0.f  - mu[j0 + 1];
    const float d2 = mom2 - mu[j0 + 2];

    float4 acc;
    acc.x = d0 * W[(j0 + 0) * 4 + 0] + d1 * W[(j0 + 1) * 4 + 0] + d2 * W[(j0 + 2) * 4 + 0];
    acc.y = d0 * W[(j0 + 0) * 4 + 1] + d1 * W[(j0 + 1) * 4 + 1] + d2 * W[(j0 + 2) * 4 + 1];
    acc.z = d0 * W[(j0 + 0) * 4 + 2] + d1 * W[(j0 + 1) * 4 + 2] + d2 * W[(j0 + 2) * 4 + 2];
    acc.w = d0 * W[(j0 + 0) * 4 + 3] + d1 * W[(j0 + 1) * 4 + 3] + d2 * W[(j0 + 2) * 4 + 3];

    __shared__ float4 sh3[576];
    sh3[c] = acc;
    __syncthreads();

    if (c < 64) {
        float4 a = sh3[c];
        for (int i = c + 64; i < 576; i += 64) {
            float4 bb = sh3[i];
            a.x += bb.x; a.y += bb.y; a.z += bb.z; a.w += bb.w;
        }
        sh3[c] = a;
    }
    __syncthreads();
    #pragma unroll
    for (int w = 32; w > 0; w >>= 1) {
        if (c < w) {
            float4 a = sh3[c], bb = sh3[c + w];
            a.x += bb.x; a.y += bb.y; a.z += bb.z; a.w += bb.w;
            sh3[c] = a;
        }
        __syncthreads();
    }

    if (c == 0) {
        out[0] = sh3[0].x;
        out[1] = sh3[0].y;
        out[2] = sh3[0].z;
        out[3] = sh3[0].w;
        // Reset barrier counters for the next graph replay. Safe: every other
        // block has already passed its final counter access and exited logic.
        g_cnt1 = 0;
        g_cnt2 = 0;
    }
}

extern "C" void kernel_launch(void* const* d_in, const int* in_sizes, int n_in,
                              void* d_out, int out_size) {
    (void)in_sizes; (void)n_in; (void)out_size;
    const float* X  = (const float*)d_in[0];   // (200000, 576)
    const float* mu = (const float*)d_in[1];   // (1728,)
    const float* W  = (const float*)d_in[2];   // (1728, 4)
    float* out = (float*)d_out;                // (1, 4)

    fused_kernel<<<NBLK, 576>>>(X, mu, W, out);
}